// round 3
// baseline (speedup 1.0000x reference)
#include <cuda_runtime.h>
#include <math.h>

#define BSZ 4
#define SEQ 2048
#define HID 1024
#define NHD 16
#define DH  64
#define TOK (BSZ*SEQ)   // 8192

// Scratch (allocation-free rule: __device__ globals)
__device__ float g_q[(size_t)TOK*HID];     // Q projection [B*S, H]
__device__ float g_stats[TOK*2];           // per-token {mu, rstd}

// ---------------------------------------------------------------------------
// Kernel 1: LayerNorm statistics (mu, rstd) per token
// ---------------------------------------------------------------------------
__global__ __launch_bounds__(256) void ln_stats_kernel(const float* __restrict__ x,
                                                       float* __restrict__ stats)
{
    int row = blockIdx.x;
    float4 v = reinterpret_cast<const float4*>(x + (size_t)row * HID)[threadIdx.x];
    float s  = v.x + v.y + v.z + v.w;
    float q  = v.x*v.x + v.y*v.y + v.z*v.z + v.w*v.w;
#pragma unroll
    for (int o = 16; o > 0; o >>= 1) {
        s += __shfl_xor_sync(0xffffffffu, s, o);
        q += __shfl_xor_sync(0xffffffffu, q, o);
    }
    __shared__ float ss[8], sq[8];
    if ((threadIdx.x & 31) == 0) { ss[threadIdx.x >> 5] = s; sq[threadIdx.x >> 5] = q; }
    __syncthreads();
    if (threadIdx.x == 0) {
        float S = 0.f, Q2 = 0.f;
#pragma unroll
        for (int i = 0; i < 8; i++) { S += ss[i]; Q2 += sq[i]; }
        float mu  = S  * (1.0f / HID);
        float var = Q2 * (1.0f / HID) - mu * mu;
        stats[2*row]     = mu;
        stats[2*row + 1] = rsqrtf(var + 1e-12f);
    }
}

// ---------------------------------------------------------------------------
// Kernel 2/4: NT SGEMM  C[M,N] = A[M,K] * W[N,K]^T
//   MODE 0: A = LayerNorm(input) applied on the fly; epilogue adds qkv bias and
//           scatters columns 0..1023 -> g_q, 1024..2047 -> out_k, 2048..3071 -> out_v
//   MODE 1: plain GEMM (output projection), writes outp
// BM=BN=128, BK=16, 256 threads, 8x8 per thread (split 4+4 for conflict-free LDS.128)
// ---------------------------------------------------------------------------
#define BM 128
#define BN 128
#define BK 16
#define SPAD 132   // transposed smem stride: 132*4B = 16B-aligned, 2-way store conflicts

template<int MODE>
__global__ __launch_bounds__(256) void gemm_nt_128(
    const float* __restrict__ A, const float* __restrict__ W,
    const float* __restrict__ bias, const float* __restrict__ stats,
    const float* __restrict__ lnw, const float* __restrict__ lnb,
    float* __restrict__ outq, float* __restrict__ outk, float* __restrict__ outv,
    float* __restrict__ outp, int Kdim)
{
    __shared__ float As[BK * SPAD];
    __shared__ float Bs[BK * SPAD];
    __shared__ float s_mu[BM], s_rs[BM];

    const int tid = threadIdx.x;
    const int tr  = tid >> 4;     // 0..15
    const int tc  = tid & 15;     // 0..15
    const int m0  = blockIdx.x * BM;
    const int n0  = blockIdx.y * BN;

    if (MODE == 0) {
        if (tid < BM) {
            s_mu[tid] = stats[2*(m0 + tid)];
            s_rs[tid] = stats[2*(m0 + tid) + 1];
        }
        __syncthreads();
    }

    float acc[8][8];
#pragma unroll
    for (int i = 0; i < 8; i++)
#pragma unroll
        for (int j = 0; j < 8; j++) acc[i][j] = 0.f;

    for (int kt = 0; kt < Kdim; kt += BK) {
        // --- A tile: 128 rows x 16 cols, transposed into As[k][m]
#pragma unroll
        for (int r = 0; r < 2; r++) {
            int f   = tid + r * 256;   // 0..511 float4 slots
            int row = f >> 2;
            int c4  = f & 3;
            float4 v = *reinterpret_cast<const float4*>(A + (size_t)(m0 + row) * Kdim + kt + c4*4);
            if (MODE == 0) {
                float mu = s_mu[row], rs = s_rs[row];
                float4 w4 = *reinterpret_cast<const float4*>(lnw + kt + c4*4);
                float4 b4 = *reinterpret_cast<const float4*>(lnb + kt + c4*4);
                v.x = (v.x - mu) * rs * w4.x + b4.x;
                v.y = (v.y - mu) * rs * w4.y + b4.y;
                v.z = (v.z - mu) * rs * w4.z + b4.z;
                v.w = (v.w - mu) * rs * w4.w + b4.w;
            }
            As[(c4*4+0)*SPAD + row] = v.x;
            As[(c4*4+1)*SPAD + row] = v.y;
            As[(c4*4+2)*SPAD + row] = v.z;
            As[(c4*4+3)*SPAD + row] = v.w;
        }
        // --- B tile: W rows n0..n0+127 x 16 cols, transposed into Bs[k][n]
#pragma unroll
        for (int r = 0; r < 2; r++) {
            int f   = tid + r * 256;
            int row = f >> 2;
            int c4  = f & 3;
            float4 v = *reinterpret_cast<const float4*>(W + (size_t)(n0 + row) * Kdim + kt + c4*4);
            Bs[(c4*4+0)*SPAD + row] = v.x;
            Bs[(c4*4+1)*SPAD + row] = v.y;
            Bs[(c4*4+2)*SPAD + row] = v.z;
            Bs[(c4*4+3)*SPAD + row] = v.w;
        }
        __syncthreads();

#pragma unroll
        for (int kk = 0; kk < BK; kk++) {
            float4 a0 = *reinterpret_cast<const float4*>(&As[kk*SPAD + tr*4]);
            float4 a1 = *reinterpret_cast<const float4*>(&As[kk*SPAD + 64 + tr*4]);
            float4 b0 = *reinterpret_cast<const float4*>(&Bs[kk*SPAD + tc*4]);
            float4 b1 = *reinterpret_cast<const float4*>(&Bs[kk*SPAD + 64 + tc*4]);
            float a[8] = {a0.x,a0.y,a0.z,a0.w,a1.x,a1.y,a1.z,a1.w};
            float b[8] = {b0.x,b0.y,b0.z,b0.w,b1.x,b1.y,b1.z,b1.w};
#pragma unroll
            for (int i = 0; i < 8; i++)
#pragma unroll
                for (int j = 0; j < 8; j++)
                    acc[i][j] = fmaf(a[i], b[j], acc[i][j]);
        }
        __syncthreads();
    }

    // --- epilogue
#pragma unroll
    for (int ih = 0; ih < 2; ih++) {
#pragma unroll
        for (int i = 0; i < 4; i++) {
            int r = m0 + ih*64 + tr*4 + i;
#pragma unroll
            for (int jh = 0; jh < 2; jh++) {
                int c = n0 + jh*64 + tc*4;
                float4 v;
                v.x = acc[ih*4+i][jh*4+0];
                v.y = acc[ih*4+i][jh*4+1];
                v.z = acc[ih*4+i][jh*4+2];
                v.w = acc[ih*4+i][jh*4+3];
                if (MODE == 0) {
                    float4 bb = *reinterpret_cast<const float4*>(&bias[c]);
                    v.x += bb.x; v.y += bb.y; v.z += bb.z; v.w += bb.w;
                    int seg = c >> 10;                 // 0:q 1:k 2:v (BN=128 never straddles)
                    float* dst = (seg == 0) ? outq : ((seg == 1) ? outk : outv);
                    *reinterpret_cast<float4*>(&dst[(size_t)r * HID + (c & 1023)]) = v;
                } else {
                    *reinterpret_cast<float4*>(&outp[(size_t)r * HID + c]) = v;
                }
            }
        }
    }
}

// ---------------------------------------------------------------------------
// Kernel 3: flash attention, 64x64 tiles, d=64, online softmax via warp shuffles
// grid (32 qtiles, 16 heads, 4 batch), 256 threads (16x16, 4x4 per thread)
// ---------------------------------------------------------------------------
#define ATT_STR 68          // 68*4B row stride: 16B-aligned float4, low conflicts
#define ATT_SMEM (3 * 64 * ATT_STR * 4)

__global__ __launch_bounds__(256) void attn_kernel(
    const float* __restrict__ Qp, const float* __restrict__ Kp,
    const float* __restrict__ Vp, const float* __restrict__ mask,
    float* __restrict__ ctx)
{
    extern __shared__ float sm[];
    float* Qst = sm;                      // [k][r] transposed, 64 x ATT_STR
    float* KV  = sm + 64 * ATT_STR;       // K: [k][n] transposed; V: [n][d]
    float* Ps  = sm + 2 * 64 * ATT_STR;   // [r][n]

    const int tid = threadIdx.x;
    const int tr  = tid >> 4;
    const int tc  = tid & 15;
    const int q0  = blockIdx.x * 64;
    const int h   = blockIdx.y;
    const int b   = blockIdx.z;

    const float* qbase = Qp + (size_t)b * SEQ * HID + h * DH;
    const float* kbase = Kp + (size_t)b * SEQ * HID + h * DH;
    const float* vbase = Vp + (size_t)b * SEQ * HID + h * DH;

    // load Q tile transposed
#pragma unroll
    for (int r = 0; r < 4; r++) {
        int f   = tid + r * 256;          // 0..1023 float4 slots
        int row = f >> 4;
        int c4  = f & 15;
        float4 v = *reinterpret_cast<const float4*>(qbase + (size_t)(q0 + row) * HID + c4*4);
        Qst[(c4*4+0)*ATT_STR + row] = v.x;
        Qst[(c4*4+1)*ATT_STR + row] = v.y;
        Qst[(c4*4+2)*ATT_STR + row] = v.z;
        Qst[(c4*4+3)*ATT_STR + row] = v.w;
    }

    float m_i[4], l_i[4], o[4][4];
#pragma unroll
    for (int i = 0; i < 4; i++) {
        m_i[i] = -INFINITY; l_i[i] = 0.f;
#pragma unroll
        for (int j = 0; j < 4; j++) o[i][j] = 0.f;
    }

    for (int nt = 0; nt < SEQ / 64; nt++) {
        const int n0 = nt * 64;
        __syncthreads();   // KV / Ps free from previous iteration
        // load K tile transposed
#pragma unroll
        for (int r = 0; r < 4; r++) {
            int f   = tid + r * 256;
            int row = f >> 4;
            int c4  = f & 15;
            float4 v = *reinterpret_cast<const float4*>(kbase + (size_t)(n0 + row) * HID + c4*4);
            KV[(c4*4+0)*ATT_STR + row] = v.x;
            KV[(c4*4+1)*ATT_STR + row] = v.y;
            KV[(c4*4+2)*ATT_STR + row] = v.z;
            KV[(c4*4+3)*ATT_STR + row] = v.w;
        }
        __syncthreads();

        // S = Q K^T (4x4 per thread)
        float s[4][4];
#pragma unroll
        for (int i = 0; i < 4; i++)
#pragma unroll
            for (int j = 0; j < 4; j++) s[i][j] = 0.f;
#pragma unroll 16
        for (int kk = 0; kk < 64; kk++) {
            float4 aq = *reinterpret_cast<const float4*>(&Qst[kk*ATT_STR + tr*4]);
            float4 bk = *reinterpret_cast<const float4*>(&KV[kk*ATT_STR + tc*4]);
            float a[4] = {aq.x, aq.y, aq.z, aq.w};
            float bb[4] = {bk.x, bk.y, bk.z, bk.w};
#pragma unroll
            for (int i = 0; i < 4; i++)
#pragma unroll
                for (int j = 0; j < 4; j++)
                    s[i][j] = fmaf(a[i], bb[j], s[i][j]);
        }

        // scale + additive mask
        float mk[4];
#pragma unroll
        for (int j = 0; j < 4; j++) mk[j] = __ldg(&mask[b * SEQ + n0 + tc*4 + j]);
#pragma unroll
        for (int i = 0; i < 4; i++)
#pragma unroll
            for (int j = 0; j < 4; j++) s[i][j] = s[i][j] * 0.125f + mk[j];

        // online softmax; row reduction across the 16 tx lanes via shfl.xor
        float mnew[4], alpha[4];
#pragma unroll
        for (int i = 0; i < 4; i++) {
            float rm = fmaxf(fmaxf(s[i][0], s[i][1]), fmaxf(s[i][2], s[i][3]));
#pragma unroll
            for (int o2 = 1; o2 < 16; o2 <<= 1)
                rm = fmaxf(rm, __shfl_xor_sync(0xffffffffu, rm, o2));
            mnew[i]  = fmaxf(m_i[i], rm);
            alpha[i] = __expf(m_i[i] - mnew[i]);
        }
#pragma unroll
        for (int i = 0; i < 4; i++) {
#pragma unroll
            for (int j = 0; j < 4; j++) s[i][j] = __expf(s[i][j] - mnew[i]);
            float rs = s[i][0] + s[i][1] + s[i][2] + s[i][3];
#pragma unroll
            for (int o2 = 1; o2 < 16; o2 <<= 1)
                rs += __shfl_xor_sync(0xffffffffu, rs, o2);
            l_i[i] = l_i[i] * alpha[i] + rs;
            m_i[i] = mnew[i];
#pragma unroll
            for (int j = 0; j < 4; j++) o[i][j] *= alpha[i];
        }
        __syncthreads();   // done reading K / previous Ps

        // store P, load V
#pragma unroll
        for (int i = 0; i < 4; i++) {
            float4 pv = {s[i][0], s[i][1], s[i][2], s[i][3]};
            *reinterpret_cast<float4*>(&Ps[(tr*4+i)*ATT_STR + tc*4]) = pv;
        }
#pragma unroll
        for (int r = 0; r < 4; r++) {
            int f   = tid + r * 256;
            int row = f >> 4;
            int c4  = f & 15;
            float4 v = *reinterpret_cast<const float4*>(vbase + (size_t)(n0 + row) * HID + c4*4);
            *reinterpret_cast<float4*>(&KV[row*ATT_STR + c4*4]) = v;
        }
        __syncthreads();

        // O += P V
#pragma unroll 8
        for (int n = 0; n < 64; n++) {
            float4 vv = *reinterpret_cast<const float4*>(&KV[n*ATT_STR + tc*4]);
            float pa0 = Ps[(tr*4+0)*ATT_STR + n];
            float pa1 = Ps[(tr*4+1)*ATT_STR + n];
            float pa2 = Ps[(tr*4+2)*ATT_STR + n];
            float pa3 = Ps[(tr*4+3)*ATT_STR + n];
            o[0][0] = fmaf(pa0, vv.x, o[0][0]); o[0][1] = fmaf(pa0, vv.y, o[0][1]);
            o[0][2] = fmaf(pa0, vv.z, o[0][2]); o[0][3] = fmaf(pa0, vv.w, o[0][3]);
            o[1][0] = fmaf(pa1, vv.x, o[1][0]); o[1][1] = fmaf(pa1, vv.y, o[1][1]);
            o[1][2] = fmaf(pa1, vv.z, o[1][2]); o[1][3] = fmaf(pa1, vv.w, o[1][3]);
            o[2][0] = fmaf(pa2, vv.x, o[2][0]); o[2][1] = fmaf(pa2, vv.y, o[2][1]);
            o[2][2] = fmaf(pa2, vv.z, o[2][2]); o[2][3] = fmaf(pa2, vv.w, o[2][3]);
            o[3][0] = fmaf(pa3, vv.x, o[3][0]); o[3][1] = fmaf(pa3, vv.y, o[3][1]);
            o[3][2] = fmaf(pa3, vv.z, o[3][2]); o[3][3] = fmaf(pa3, vv.w, o[3][3]);
        }
    }

    // write context (final 1/l normalization)
#pragma unroll
    for (int i = 0; i < 4; i++) {
        float inv = 1.0f / l_i[i];
        float4 ov = {o[i][0]*inv, o[i][1]*inv, o[i][2]*inv, o[i][3]*inv};
        *reinterpret_cast<float4*>(
            &ctx[(size_t)(b * SEQ + q0 + tr*4 + i) * HID + h * DH + tc*4]) = ov;
    }
}

// ---------------------------------------------------------------------------
extern "C" void kernel_launch(void* const* d_in, const int* in_sizes, int n_in,
                              void* d_out, int out_size)
{
    const float* input = (const float*)d_in[0];
    const float* mask  = (const float*)d_in[1];
    const float* nw    = (const float*)d_in[2];
    const float* nb    = (const float*)d_in[3];
    const float* qkvw  = (const float*)d_in[4];
    const float* qkvb  = (const float*)d_in[5];
    const float* ow    = (const float*)d_in[6];

    float* out   = (float*)d_out;
    float* out_o = out;
    float* out_k = out + (size_t)TOK * HID;
    float* out_v = out + 2 * (size_t)TOK * HID;
    float* out_c = out + 3 * (size_t)TOK * HID;

    float *gq = nullptr, *gst = nullptr;
    cudaGetSymbolAddress((void**)&gq, g_q);
    cudaGetSymbolAddress((void**)&gst, g_stats);

    cudaFuncSetAttribute(attn_kernel, cudaFuncAttributeMaxDynamicSharedMemorySize, ATT_SMEM);

    ln_stats_kernel<<<TOK, 256>>>(input, gst);
    gemm_nt_128<0><<<dim3(TOK/BM, 3*HID/BN), 256>>>(input, qkvw, qkvb, gst, nw, nb,
                                                    gq, out_k, out_v, nullptr, HID);
    attn_kernel<<<dim3(SEQ/64, NHD, BSZ), 256, ATT_SMEM>>>(gq, out_k, out_v, mask, out_c);
    gemm_nt_128<1><<<dim3(TOK/BM, HID/BN), 256>>>(out_c, ow, nullptr, nullptr, nullptr, nullptr,
                                                  nullptr, nullptr, nullptr, out_o, HID);
}

// round 5
// speedup vs baseline: 2.5611x; 2.5611x over previous
#include <cuda_runtime.h>
#include <math.h>
#include <stdint.h>

#define BSZ 4
#define SEQ 2048
#define HID 1024
#define NHD 16
#define DH  64
#define TOK (BSZ*SEQ)   // 8192

// Scratch (allocation-free rule: __device__ globals)
__device__ float g_q[(size_t)TOK*HID];    // Q projection [B*S, H]
__device__ float g_ln[(size_t)TOK*HID];   // LayerNorm(input) [B*S, H]

// ===========================================================================
// helpers
// ===========================================================================
__device__ __forceinline__ uint32_t s2u(const void* p) {
    uint32_t a;
    asm("{ .reg .u64 t; cvta.to.shared.u64 t, %1; cvt.u32.u64 %0, t; }"
        : "=r"(a) : "l"(p));
    return a;
}
__device__ __forceinline__ uint32_t f2tf(float x) {
    uint32_t r;
    asm("cvt.rna.tf32.f32 %0, %1;" : "=r"(r) : "f"(x));
    return r;
}
// D += A*B, m16n8k8 tf32
__device__ __forceinline__ void mma_tf32(float* d, const uint32_t* a, const uint32_t* b) {
    asm volatile(
        "mma.sync.aligned.m16n8k8.row.col.f32.tf32.tf32.f32 "
        "{%0,%1,%2,%3}, {%4,%5,%6,%7}, {%8,%9}, {%0,%1,%2,%3};"
        : "+f"(d[0]), "+f"(d[1]), "+f"(d[2]), "+f"(d[3])
        : "r"(a[0]), "r"(a[1]), "r"(a[2]), "r"(a[3]), "r"(b[0]), "r"(b[1]));
}
#define CP_ASYNC16(dst, src) \
    asm volatile("cp.async.cg.shared.global [%0], [%1], 16;" :: "r"(dst), "l"(src))
#define CP_COMMIT() asm volatile("cp.async.commit_group;" ::: "memory")
#define CP_WAIT(n)  asm volatile("cp.async.wait_group %0;" :: "n"(n) : "memory")

// ===========================================================================
// Kernel 1: LayerNorm (fused stats + normalize) -> g_ln
// ===========================================================================
__global__ __launch_bounds__(256) void ln_kernel(const float* __restrict__ x,
                                                 const float* __restrict__ w,
                                                 const float* __restrict__ bb,
                                                 float* __restrict__ y)
{
    int row = blockIdx.x;
    int t = threadIdx.x;
    float4 v = reinterpret_cast<const float4*>(x + (size_t)row * HID)[t];
    float s = v.x + v.y + v.z + v.w;
    float q = v.x*v.x + v.y*v.y + v.z*v.z + v.w*v.w;
#pragma unroll
    for (int o = 16; o > 0; o >>= 1) {
        s += __shfl_xor_sync(0xffffffffu, s, o);
        q += __shfl_xor_sync(0xffffffffu, q, o);
    }
    __shared__ float ss[8], sq[8], smu, srs;
    if ((t & 31) == 0) { ss[t >> 5] = s; sq[t >> 5] = q; }
    __syncthreads();
    if (t == 0) {
        float S = 0.f, Q2 = 0.f;
#pragma unroll
        for (int i = 0; i < 8; i++) { S += ss[i]; Q2 += sq[i]; }
        float mu = S * (1.0f / HID);
        smu = mu;
        srs = rsqrtf(Q2 * (1.0f / HID) - mu * mu + 1e-12f);
    }
    __syncthreads();
    float mu = smu, rs = srs;
    float4 w4 = reinterpret_cast<const float4*>(w)[t];
    float4 b4 = reinterpret_cast<const float4*>(bb)[t];
    float4 o;
    o.x = (v.x - mu) * rs * w4.x + b4.x;
    o.y = (v.y - mu) * rs * w4.y + b4.y;
    o.z = (v.z - mu) * rs * w4.z + b4.z;
    o.w = (v.w - mu) * rs * w4.w + b4.w;
    reinterpret_cast<float4*>(y + (size_t)row * HID)[t] = o;
}

// ===========================================================================
// Kernel 2/4: tf32 mma.sync GEMM  C[M,N] = A[M,K] * W[N,K]^T
//   128x128 CTA tile, 256 thr, 8 warps (4 along M x 2 along N), warp 32x64.
//   BK=16, 3-stage cp.async pipeline, smem word stride 20 (conflict-free frags)
//   MODE 0: +bias, scatter cols 0..1023->outq / ..2047->outk / ..3071->outv
//   MODE 1: plain, writes outp
// ===========================================================================
#define GST  3
#define ASTR 20
#define TILEW (128*ASTR)           // 2560 words per tile
#define SSZ   (2*TILEW)            // 5120 words per stage (A + B)
#define GEMM_SMEM (GST*SSZ*4)      // 61440 B

template<int MODE>
__global__ __launch_bounds__(256, 2) void gemm_mma(
    const float* __restrict__ Ap, const float* __restrict__ W,
    const float* __restrict__ bias,
    float* __restrict__ outq, float* __restrict__ outk,
    float* __restrict__ outv, float* __restrict__ outp)
{
    extern __shared__ float smf[];
    const uint32_t smb = s2u(smf);

    const int tid = threadIdx.x;
    const int wid = tid >> 5, lane = tid & 31;
    const int g = lane >> 2, tig = lane & 3;
    const int wM = wid & 3, wN = wid >> 2;
    const int m0 = blockIdx.x * 128, n0 = blockIdx.y * 128;
    const int NK = HID / 16;   // 64

    float acc[2][8][4];
#pragma unroll
    for (int a = 0; a < 2; a++)
#pragma unroll
        for (int b = 0; b < 8; b++)
#pragma unroll
            for (int c = 0; c < 4; c++) acc[a][b][c] = 0.f;

    // ---- async tile loader: 1024 16B chunks (A:512, B:512), 4 per thread
    auto load_stage = [&](int s, int kt) {
        uint32_t base = smb + (uint32_t)s * SSZ * 4;
#pragma unroll
        for (int j = 0; j < 4; j++) {
            int ci  = tid + j * 256;
            int tb  = ci >> 9;            // 0 = A, 1 = B
            int row = (ci >> 2) & 127;
            int c   = ci & 3;
            const float* src = (tb ? (W  + (size_t)(n0 + row) * HID)
                                   : (Ap + (size_t)(m0 + row) * HID)) + kt * 16 + c * 4;
            uint32_t dst = base + (uint32_t)(tb * TILEW + row * ASTR + c * 4) * 4;
            CP_ASYNC16(dst, src);
        }
    };

#pragma unroll
    for (int p = 0; p < GST - 1; p++) { load_stage(p, p); CP_COMMIT(); }

    for (int kt = 0; kt < NK; kt++) {
        __syncthreads();                        // stage (kt-1)%GST free for overwrite
        if (kt + GST - 1 < NK) load_stage((kt + GST - 1) % GST, kt + GST - 1);
        CP_COMMIT();
        CP_WAIT(GST - 1);                       // stage kt%GST data arrived
        __syncthreads();

        const float* As = smf + (kt % GST) * SSZ;
        const float* Bs = As + TILEW;
#pragma unroll
        for (int ks = 0; ks < 2; ks++) {
            const int ko = ks * 8;
            uint32_t af[2][4], bf[8][2];
#pragma unroll
            for (int mt = 0; mt < 2; mt++) {
                int r = wM * 32 + mt * 16;
                af[mt][0] = f2tf(As[(r + g)     * ASTR + ko + tig]);
                af[mt][1] = f2tf(As[(r + 8 + g) * ASTR + ko + tig]);
                af[mt][2] = f2tf(As[(r + g)     * ASTR + ko + tig + 4]);
                af[mt][3] = f2tf(As[(r + 8 + g) * ASTR + ko + tig + 4]);
            }
#pragma unroll
            for (int nt = 0; nt < 8; nt++) {
                int n = wN * 64 + nt * 8 + g;
                bf[nt][0] = f2tf(Bs[n * ASTR + ko + tig]);
                bf[nt][1] = f2tf(Bs[n * ASTR + ko + tig + 4]);
            }
#pragma unroll
            for (int mt = 0; mt < 2; mt++)
#pragma unroll
                for (int nt = 0; nt < 8; nt++)
                    mma_tf32(acc[mt][nt], af[mt], bf[nt]);
        }
    }

    // ---- epilogue
#pragma unroll
    for (int nt = 0; nt < 8; nt++) {
        int cb = n0 + wN * 64 + nt * 8 + 2 * tig;
        float2 bv = {0.f, 0.f};
        float* dst; int col;
        if (MODE == 0) {
            bv = *reinterpret_cast<const float2*>(bias + cb);
            int seg = cb >> 10;
            col = cb & 1023;
            dst = (seg == 0) ? outq : ((seg == 1) ? outk : outv);
        } else { dst = outp; col = cb; }
#pragma unroll
        for (int mt = 0; mt < 2; mt++) {
            int r = m0 + wM * 32 + mt * 16 + g;
            float2 v0 = {acc[mt][nt][0] + bv.x, acc[mt][nt][1] + bv.y};
            float2 v1 = {acc[mt][nt][2] + bv.x, acc[mt][nt][3] + bv.y};
            *reinterpret_cast<float2*>(dst + (size_t)r * HID + col)       = v0;
            *reinterpret_cast<float2*>(dst + (size_t)(r + 8) * HID + col) = v1;
        }
    }
}

// ===========================================================================
// Kernel 3: flash attention with tf32 mma.sync
//   256 thr (8 warps), q-tile 128 (16 rows/warp, Q frags in regs), kv-tile 64
//   smem: Ks[64][68] | Vs[64][72] | Ps[128][68] | ms[64]
// ===========================================================================
#define KSTR 68
#define VSTR 72
#define PSTR 68
#define KS_OFF 0
#define VS_OFF (64*KSTR)                   // 4352
#define PS_OFF (VS_OFF + 64*VSTR)          // 8960
#define MS_OFF (PS_OFF + 128*PSTR)         // 17664
#define ATT_SMEM ((MS_OFF + 80) * 4)       // ~71 KB

__global__ __launch_bounds__(256) void attn_mma(
    const float* __restrict__ Qp, const float* __restrict__ Kp,
    const float* __restrict__ Vp, const float* __restrict__ mask,
    float* __restrict__ ctx)
{
    extern __shared__ float smf[];
    float* Ks = smf + KS_OFF;
    float* Vs = smf + VS_OFF;
    float* Ps = smf + PS_OFF;
    float* ms = smf + MS_OFF;
    const uint32_t smb = s2u(smf);

    const int tid = threadIdx.x;
    const int wid = tid >> 5, lane = tid & 31;
    const int g = lane >> 2, tig = lane & 3;
    const int q0 = blockIdx.x * 128;
    const int h  = blockIdx.y;
    const int b  = blockIdx.z;

    const float* qbase = Qp + (size_t)b * SEQ * HID + h * DH;
    const float* kbase = Kp + (size_t)b * SEQ * HID + h * DH;
    const float* vbase = Vp + (size_t)b * SEQ * HID + h * DH;

    const float L2E = 1.4426950408889634f;
    const float SCL = 0.125f * L2E;

    // ---- stage Q tile (128x64) into Ps area, then lift per-warp frags to regs
#pragma unroll
    for (int j = 0; j < 8; j++) {
        int ci = tid + j * 256;          // 0..2047 float4 chunks
        int row = ci >> 4, c4 = ci & 15;
        float4 v = *reinterpret_cast<const float4*>(qbase + (size_t)(q0 + row) * HID + c4 * 4);
        *reinterpret_cast<float4*>(&Ps[row * PSTR + c4 * 4]) = v;
    }
    __syncthreads();
    uint32_t qf[8][4];
#pragma unroll
    for (int kt = 0; kt < 8; kt++) {
        int r = wid * 16;
        qf[kt][0] = f2tf(Ps[(r + g)     * PSTR + kt * 8 + tig]);
        qf[kt][1] = f2tf(Ps[(r + 8 + g) * PSTR + kt * 8 + tig]);
        qf[kt][2] = f2tf(Ps[(r + g)     * PSTR + kt * 8 + tig + 4]);
        qf[kt][3] = f2tf(Ps[(r + 8 + g) * PSTR + kt * 8 + tig + 4]);
    }
    __syncthreads();

    float m0r = -1e30f, m1r = -1e30f, l0 = 0.f, l1 = 0.f;
    float oacc[8][4];
#pragma unroll
    for (int i = 0; i < 8; i++)
#pragma unroll
        for (int j = 0; j < 4; j++) oacc[i][j] = 0.f;

    for (int nt = 0; nt < SEQ / 64; nt++) {
        const int n0 = nt * 64;
        // ---- K,V tiles via cp.async (64x64 each, 16B chunks, 8 per thread)
#pragma unroll
        for (int j = 0; j < 4; j++) {
            int ci = tid + j * 256;
            int row = ci >> 4, c = ci & 15;
            CP_ASYNC16(smb + (uint32_t)(KS_OFF + row * KSTR + c * 4) * 4,
                       kbase + (size_t)(n0 + row) * HID + c * 4);
            CP_ASYNC16(smb + (uint32_t)(VS_OFF + row * VSTR + c * 4) * 4,
                       vbase + (size_t)(n0 + row) * HID + c * 4);
        }
        if (tid < 16) {
            float4 mv = *reinterpret_cast<const float4*>(mask + (size_t)b * SEQ + n0 + tid * 4);
            mv.x *= L2E; mv.y *= L2E; mv.z *= L2E; mv.w *= L2E;
            *reinterpret_cast<float4*>(&ms[tid * 4]) = mv;
        }
        CP_COMMIT();
        CP_WAIT(0);
        __syncthreads();

        // ---- S = Q K^T  (8 n-tiles x 8 k-steps)
        float sf[8][4];
#pragma unroll
        for (int i = 0; i < 8; i++)
#pragma unroll
            for (int j = 0; j < 4; j++) sf[i][j] = 0.f;
#pragma unroll
        for (int kt = 0; kt < 8; kt++) {
#pragma unroll
            for (int sn = 0; sn < 8; sn++) {
                uint32_t kb[2];
                kb[0] = f2tf(Ks[(sn * 8 + g) * KSTR + kt * 8 + tig]);
                kb[1] = f2tf(Ks[(sn * 8 + g) * KSTR + kt * 8 + tig + 4]);
                mma_tf32(sf[sn], qf[kt], kb);
            }
        }

        // ---- online softmax (base-2 domain)
        float zmax0 = -1e30f, zmax1 = -1e30f;
#pragma unroll
        for (int sn = 0; sn < 8; sn++) {
            float mc0 = ms[sn * 8 + 2 * tig], mc1 = ms[sn * 8 + 2 * tig + 1];
            sf[sn][0] = sf[sn][0] * SCL + mc0;
            sf[sn][1] = sf[sn][1] * SCL + mc1;
            sf[sn][2] = sf[sn][2] * SCL + mc0;
            sf[sn][3] = sf[sn][3] * SCL + mc1;
            zmax0 = fmaxf(zmax0, fmaxf(sf[sn][0], sf[sn][1]));
            zmax1 = fmaxf(zmax1, fmaxf(sf[sn][2], sf[sn][3]));
        }
#pragma unroll
        for (int o2 = 1; o2 < 4; o2 <<= 1) {
            zmax0 = fmaxf(zmax0, __shfl_xor_sync(0xffffffffu, zmax0, o2));
            zmax1 = fmaxf(zmax1, __shfl_xor_sync(0xffffffffu, zmax1, o2));
        }
        float mn0 = fmaxf(m0r, zmax0), mn1 = fmaxf(m1r, zmax1);
        float al0 = exp2f(m0r - mn0), al1 = exp2f(m1r - mn1);
        m0r = mn0; m1r = mn1;

        float rs0 = 0.f, rs1 = 0.f;
        const int pr = wid * 16;
#pragma unroll
        for (int sn = 0; sn < 8; sn++) {
            float p0 = exp2f(sf[sn][0] - mn0);
            float p1 = exp2f(sf[sn][1] - mn0);
            float p2 = exp2f(sf[sn][2] - mn1);
            float p3 = exp2f(sf[sn][3] - mn1);
            rs0 += p0 + p1; rs1 += p2 + p3;
            uint2 w0 = {f2tf(p0), f2tf(p1)};
            uint2 w1 = {f2tf(p2), f2tf(p3)};
            *reinterpret_cast<uint2*>(&Ps[(pr + g)     * PSTR + sn * 8 + 2 * tig]) = w0;
            *reinterpret_cast<uint2*>(&Ps[(pr + 8 + g) * PSTR + sn * 8 + 2 * tig]) = w1;
        }
#pragma unroll
        for (int o2 = 1; o2 < 4; o2 <<= 1) {
            rs0 += __shfl_xor_sync(0xffffffffu, rs0, o2);
            rs1 += __shfl_xor_sync(0xffffffffu, rs1, o2);
        }
        l0 = l0 * al0 + rs0;
        l1 = l1 * al1 + rs1;
#pragma unroll
        for (int dn = 0; dn < 8; dn++) {
            oacc[dn][0] *= al0; oacc[dn][1] *= al0;
            oacc[dn][2] *= al1; oacc[dn][3] *= al1;
        }
        __syncwarp();   // P stores visible to warp before A-frag reads

        // ---- O += P V  (8 kv k-tiles x 8 d n-tiles)
#pragma unroll
        for (int kt = 0; kt < 8; kt++) {
            uint32_t pa[4];
            pa[0] = __float_as_uint(Ps[(pr + g)     * PSTR + kt * 8 + tig]);
            pa[1] = __float_as_uint(Ps[(pr + 8 + g) * PSTR + kt * 8 + tig]);
            pa[2] = __float_as_uint(Ps[(pr + g)     * PSTR + kt * 8 + tig + 4]);
            pa[3] = __float_as_uint(Ps[(pr + 8 + g) * PSTR + kt * 8 + tig + 4]);
#pragma unroll
            for (int dn = 0; dn < 8; dn++) {
                uint32_t vb[2];
                vb[0] = f2tf(Vs[(kt * 8 + tig)     * VSTR + dn * 8 + g]);
                vb[1] = f2tf(Vs[(kt * 8 + tig + 4) * VSTR + dn * 8 + g]);
                mma_tf32(oacc[dn], pa, vb);
            }
        }
        __syncthreads();   // before next tile's K/V overwrite
    }

    // ---- write context
    float inv0 = 1.0f / l0, inv1 = 1.0f / l1;
    int r0 = b * SEQ + q0 + wid * 16 + g;
#pragma unroll
    for (int dn = 0; dn < 8; dn++) {
        int col = h * DH + dn * 8 + 2 * tig;
        float2 v0 = {oacc[dn][0] * inv0, oacc[dn][1] * inv0};
        float2 v1 = {oacc[dn][2] * inv1, oacc[dn][3] * inv1};
        *reinterpret_cast<float2*>(ctx + (size_t)r0 * HID + col)       = v0;
        *reinterpret_cast<float2*>(ctx + (size_t)(r0 + 8) * HID + col) = v1;
    }
}

// ===========================================================================
// Host side
// ===========================================================================
extern "C" void kernel_launch(void* const* d_in, const int* in_sizes, int n_in,
                              void* d_out, int out_size)
{
    const float* input = (const float*)d_in[0];
    const float* mask  = (const float*)d_in[1];
    const float* nw    = (const float*)d_in[2];
    const float* nb    = (const float*)d_in[3];
    const float* qkvw  = (const float*)d_in[4];
    const float* qkvb  = (const float*)d_in[5];
    const float* ow    = (const float*)d_in[6];

    float* out   = (float*)d_out;
    float* out_o = out;
    float* out_k = out + (size_t)TOK * HID;
    float* out_v = out + 2 * (size_t)TOK * HID;
    float* out_c = out + 3 * (size_t)TOK * HID;

    float *gq = nullptr, *gln = nullptr;
    cudaGetSymbolAddress((void**)&gq, g_q);
    cudaGetSymbolAddress((void**)&gln, g_ln);

    cudaFuncSetAttribute(gemm_mma<0>, cudaFuncAttributeMaxDynamicSharedMemorySize, GEMM_SMEM);
    cudaFuncSetAttribute(gemm_mma<1>, cudaFuncAttributeMaxDynamicSharedMemorySize, GEMM_SMEM);
    cudaFuncSetAttribute(attn_mma,    cudaFuncAttributeMaxDynamicSharedMemorySize, ATT_SMEM);

    ln_kernel<<<TOK, 256>>>(input, nw, nb, gln);
    gemm_mma<0><<<dim3(TOK/128, 3*HID/128), 256, GEMM_SMEM>>>(
        gln, qkvw, qkvb, gq, out_k, out_v, nullptr);
    attn_mma<<<dim3(SEQ/128, NHD, BSZ), 256, ATT_SMEM>>>(gq, out_k, out_v, mask, out_c);
    gemm_mma<1><<<dim3(TOK/128, HID/128), 256, GEMM_SMEM>>>(
        out_c, ow, nullptr, nullptr, nullptr, nullptr, out_o);
}

// round 6
// speedup vs baseline: 3.4650x; 1.3529x over previous
#include <cuda_runtime.h>
#include <math.h>
#include <stdint.h>

#define BSZ 4
#define SEQ 2048
#define HID 1024
#define NHD 16
#define DH  64
#define TOK (BSZ*SEQ)   // 8192

// Scratch (allocation-free rule: __device__ globals). All "*_r" hold
// tf32-pre-rounded f32 bit patterns (valid operands for mma tf32).
__device__ float g_q  [(size_t)TOK*HID];    // Q projection, rounded
__device__ float g_ln [(size_t)TOK*HID];    // LayerNorm(input), rounded
__device__ float g_kr [(size_t)TOK*HID];    // K rounded copy
__device__ float g_vr [(size_t)TOK*HID];    // V rounded copy
__device__ float g_cr [(size_t)TOK*HID];    // context rounded copy
__device__ float g_wq [(size_t)3*HID*HID];  // qkv weights rounded
__device__ float g_wo [(size_t)HID*HID];    // out-proj weights rounded

// ===========================================================================
// helpers
// ===========================================================================
__device__ __forceinline__ uint32_t s2u(const void* p) {
    uint32_t a;
    asm("{ .reg .u64 t; cvta.to.shared.u64 t, %1; cvt.u32.u64 %0, t; }"
        : "=r"(a) : "l"(p));
    return a;
}
__device__ __forceinline__ uint32_t f2tf(float x) {
    uint32_t r;
    asm("cvt.rna.tf32.f32 %0, %1;" : "=r"(r) : "f"(x));
    return r;
}
__device__ __forceinline__ float f2tff(float x) { return __uint_as_float(f2tf(x)); }

// D += A*B, m16n8k8 tf32
__device__ __forceinline__ void mma_tf32(float* d, const uint32_t* a, const uint32_t* b) {
    asm volatile(
        "mma.sync.aligned.m16n8k8.row.col.f32.tf32.tf32.f32 "
        "{%0,%1,%2,%3}, {%4,%5,%6,%7}, {%8,%9}, {%0,%1,%2,%3};"
        : "+f"(d[0]), "+f"(d[1]), "+f"(d[2]), "+f"(d[3])
        : "r"(a[0]), "r"(a[1]), "r"(a[2]), "r"(a[3]), "r"(b[0]), "r"(b[1]));
}
#define CP_ASYNC16(dst, src) \
    asm volatile("cp.async.cg.shared.global [%0], [%1], 16;" :: "r"(dst), "l"(src))
#define CP_COMMIT() asm volatile("cp.async.commit_group;" ::: "memory")
#define CP_WAIT(n)  asm volatile("cp.async.wait_group %0;" :: "n"(n) : "memory")

// ===========================================================================
// Kernel 0: round weights to tf32 (grid-stride float4)
// ===========================================================================
__global__ __launch_bounds__(256) void round4_kernel(const float* __restrict__ src,
                                                     float* __restrict__ dst, int n4)
{
    int i = blockIdx.x * blockDim.x + threadIdx.x;
    if (i < n4) {
        float4 v = reinterpret_cast<const float4*>(src)[i];
        v.x = f2tff(v.x); v.y = f2tff(v.y); v.z = f2tff(v.z); v.w = f2tff(v.w);
        reinterpret_cast<float4*>(dst)[i] = v;
    }
}

// ===========================================================================
// Kernel 1: LayerNorm -> g_ln (tf32-rounded)
// ===========================================================================
__global__ __launch_bounds__(256) void ln_kernel(const float* __restrict__ x,
                                                 const float* __restrict__ w,
                                                 const float* __restrict__ bb,
                                                 float* __restrict__ y)
{
    int row = blockIdx.x;
    int t = threadIdx.x;
    float4 v = reinterpret_cast<const float4*>(x + (size_t)row * HID)[t];
    float s = v.x + v.y + v.z + v.w;
    float q = v.x*v.x + v.y*v.y + v.z*v.z + v.w*v.w;
#pragma unroll
    for (int o = 16; o > 0; o >>= 1) {
        s += __shfl_xor_sync(0xffffffffu, s, o);
        q += __shfl_xor_sync(0xffffffffu, q, o);
    }
    __shared__ float ss[8], sq[8], smu, srs;
    if ((t & 31) == 0) { ss[t >> 5] = s; sq[t >> 5] = q; }
    __syncthreads();
    if (t == 0) {
        float S = 0.f, Q2 = 0.f;
#pragma unroll
        for (int i = 0; i < 8; i++) { S += ss[i]; Q2 += sq[i]; }
        float mu = S * (1.0f / HID);
        smu = mu;
        srs = rsqrtf(Q2 * (1.0f / HID) - mu * mu + 1e-12f);
    }
    __syncthreads();
    float mu = smu, rs = srs;
    float4 w4 = reinterpret_cast<const float4*>(w)[t];
    float4 b4 = reinterpret_cast<const float4*>(bb)[t];
    float4 o;
    o.x = f2tff((v.x - mu) * rs * w4.x + b4.x);
    o.y = f2tff((v.y - mu) * rs * w4.y + b4.y);
    o.z = f2tff((v.z - mu) * rs * w4.z + b4.z);
    o.w = f2tff((v.w - mu) * rs * w4.w + b4.w);
    reinterpret_cast<float4*>(y + (size_t)row * HID)[t] = o;
}

// ===========================================================================
// Kernel 2/4: tf32 mma.sync GEMM  C[M,N] = A[M,K] * W[N,K]^T
//   Inputs pre-rounded -> NO cvt in the mainloop.
//   128x128 CTA, 256 thr, 8 warps (4M x 2N), warp 32x64.
//   BK=32, 2-stage cp.async double-buffer, smem word stride 36 (CF frags).
//   MODE 0: +bias; q->outq(rounded), k->outk(exact)+outkr(rounded),
//           v->outv(exact)+outvr(rounded)
//   MODE 1: plain, writes outp
// ===========================================================================
#define WSTR  36
#define GTILEW (128*WSTR)          // 4608 words per tile
#define GSSZ   (2*GTILEW)          // 9216 words per stage (A+B)
#define GEMM_SMEM (2*GSSZ*4)       // 73728 B

template<int MODE>
__global__ __launch_bounds__(256, 2) void gemm_mma(
    const float* __restrict__ Ap, const float* __restrict__ W,
    const float* __restrict__ bias,
    float* __restrict__ outq,
    float* __restrict__ outk, float* __restrict__ outkr,
    float* __restrict__ outv, float* __restrict__ outvr,
    float* __restrict__ outp)
{
    extern __shared__ float smf[];
    const uint32_t smb = s2u(smf);

    const int tid = threadIdx.x;
    const int wid = tid >> 5, lane = tid & 31;
    const int g = lane >> 2, tig = lane & 3;
    const int wM = wid & 3, wN = wid >> 2;
    const int m0 = blockIdx.x * 128, n0 = blockIdx.y * 128;
    const int NT = HID / 32;   // 32

    float acc[2][8][4];
#pragma unroll
    for (int a = 0; a < 2; a++)
#pragma unroll
        for (int b = 0; b < 8; b++)
#pragma unroll
            for (int c = 0; c < 4; c++) acc[a][b][c] = 0.f;

    // ---- async tile loader: 2048 16B chunks (A:1024, B:1024), 8/thread
    auto load_stage = [&](int s, int kt) {
        uint32_t base = smb + (uint32_t)s * GSSZ * 4;
#pragma unroll
        for (int j = 0; j < 8; j++) {
            int ci  = tid + j * 256;
            int tb  = ci >> 10;           // 0 = A, 1 = B
            int row = (ci >> 3) & 127;
            int c   = ci & 7;
            const float* src = (tb ? (W  + (size_t)(n0 + row) * HID)
                                   : (Ap + (size_t)(m0 + row) * HID)) + kt * 32 + c * 4;
            uint32_t dst = base + (uint32_t)(tb * GTILEW + row * WSTR + c * 4) * 4;
            CP_ASYNC16(dst, src);
        }
    };

    load_stage(0, 0); CP_COMMIT();
    load_stage(1, 1); CP_COMMIT();

    for (int kt = 0; kt < NT; kt++) {
        CP_WAIT(1);
        __syncthreads();                      // stage kt&1 data visible
        const float* As = smf + (kt & 1) * GSSZ;
        const float* Bs = As + GTILEW;
#pragma unroll
        for (int ks = 0; ks < 4; ks++) {
            const int ko = ks * 8;
            uint32_t af[2][4], bf[8][2];
#pragma unroll
            for (int mt = 0; mt < 2; mt++) {
                int r = wM * 32 + mt * 16;
                af[mt][0] = __float_as_uint(As[(r + g)     * WSTR + ko + tig]);
                af[mt][1] = __float_as_uint(As[(r + 8 + g) * WSTR + ko + tig]);
                af[mt][2] = __float_as_uint(As[(r + g)     * WSTR + ko + tig + 4]);
                af[mt][3] = __float_as_uint(As[(r + 8 + g) * WSTR + ko + tig + 4]);
            }
#pragma unroll
            for (int nt = 0; nt < 8; nt++) {
                int n = wN * 64 + nt * 8 + g;
                bf[nt][0] = __float_as_uint(Bs[n * WSTR + ko + tig]);
                bf[nt][1] = __float_as_uint(Bs[n * WSTR + ko + tig + 4]);
            }
#pragma unroll
            for (int mt = 0; mt < 2; mt++)
#pragma unroll
                for (int nt = 0; nt < 8; nt++)
                    mma_tf32(acc[mt][nt], af[mt], bf[nt]);
        }
        __syncthreads();                      // all warps done reading stage kt&1
        if (kt + 2 < NT) load_stage(kt & 1, kt + 2);
        CP_COMMIT();                          // (possibly empty) keeps group math uniform
    }

    // ---- epilogue
#pragma unroll
    for (int nt = 0; nt < 8; nt++) {
        int cb = n0 + wN * 64 + nt * 8 + 2 * tig;
        float2 bv = {0.f, 0.f};
        int seg = 0, col = cb;
        if (MODE == 0) {
            bv = *reinterpret_cast<const float2*>(bias + cb);
            seg = cb >> 10;
            col = cb & 1023;
        }
#pragma unroll
        for (int mt = 0; mt < 2; mt++) {
            int r = m0 + wM * 32 + mt * 16 + g;
#pragma unroll
            for (int hh = 0; hh < 2; hh++) {
                size_t off = (size_t)(r + hh * 8) * HID + col;
                float2 v = {acc[mt][nt][2*hh+0] + bv.x, acc[mt][nt][2*hh+1] + bv.y};
                if (MODE == 0) {
                    float2 vr = {f2tff(v.x), f2tff(v.y)};
                    if (seg == 0) {
                        *reinterpret_cast<float2*>(outq + off) = vr;
                    } else if (seg == 1) {
                        *reinterpret_cast<float2*>(outk  + off) = v;
                        *reinterpret_cast<float2*>(outkr + off) = vr;
                    } else {
                        *reinterpret_cast<float2*>(outv  + off) = v;
                        *reinterpret_cast<float2*>(outvr + off) = vr;
                    }
                } else {
                    *reinterpret_cast<float2*>(outp + off) = v;
                }
            }
        }
    }
}

// ===========================================================================
// Kernel 3: flash attention, tf32 mma.sync, 2-stage cp.async KV pipeline.
//   Inputs pre-rounded -> no cvt on K/V/Q fragments.
//   256 thr (8 warps x 16 q-rows), q-tile 128, kv-tile 64.
//   stage: Ks[64][68] | Vs[64][72] | ms[64]  (x2) ; Ps[128][68]
// ===========================================================================
#define KSTR 68
#define VSTR 72
#define PSTR 68
#define STGW (64*KSTR + 64*VSTR + 64)       // 9024 words per stage
#define VOFF (64*KSTR)                      // 4352
#define MOFF (64*KSTR + 64*VSTR)            // 8960
#define PS_OFF (2*STGW)                     // 18048
#define ATT_SMEM ((PS_OFF + 128*PSTR) * 4)  // 106,816 B

__global__ __launch_bounds__(256) void attn_mma(
    const float* __restrict__ Qp, const float* __restrict__ Kp,
    const float* __restrict__ Vp, const float* __restrict__ mask,
    float* __restrict__ ctx, float* __restrict__ ctxr)
{
    extern __shared__ float smf[];
    float* Ps = smf + PS_OFF;
    const uint32_t smb = s2u(smf);

    const int tid = threadIdx.x;
    const int wid = tid >> 5, lane = tid & 31;
    const int g = lane >> 2, tig = lane & 3;
    const int q0 = blockIdx.x * 128;
    const int h  = blockIdx.y;
    const int b  = blockIdx.z;
    const int NT = SEQ / 64;   // 32

    const float* qbase = Qp + (size_t)b * SEQ * HID + h * DH;
    const float* kbase = Kp + (size_t)b * SEQ * HID + h * DH;
    const float* vbase = Vp + (size_t)b * SEQ * HID + h * DH;

    const float L2E = 1.4426950408889634f;
    const float SCL = 0.125f * L2E;

    // ---- KV tile issue (cp.async): K 1024 + V 1024 chunks, 8/thread; mask 16
    auto issue_tile = [&](int nt) {
        int s = nt & 1;
        uint32_t base = smb + (uint32_t)s * STGW * 4;
        int n0 = nt * 64;
#pragma unroll
        for (int j = 0; j < 8; j++) {
            int ci  = tid + j * 256;
            int tb  = ci >> 10;               // 0 = K, 1 = V
            int row = (ci >> 4) & 63;
            int c   = ci & 15;
            const float* src = (tb ? vbase : kbase) + (size_t)(n0 + row) * HID + c * 4;
            uint32_t dst = base + (uint32_t)(tb ? (VOFF + row * VSTR + c * 4)
                                                : (row * KSTR + c * 4)) * 4;
            CP_ASYNC16(dst, src);
        }
        if (tid < 16)
            CP_ASYNC16(base + (uint32_t)(MOFF + tid * 4) * 4,
                       mask + (size_t)b * SEQ + n0 + tid * 4);
    };

    issue_tile(0); CP_COMMIT();
    issue_tile(1); CP_COMMIT();

    // ---- stage Q tile (128x64) into Ps, lift per-warp frags to regs
#pragma unroll
    for (int j = 0; j < 8; j++) {
        int ci = tid + j * 256;
        int row = ci >> 4, c4 = ci & 15;
        float4 v = *reinterpret_cast<const float4*>(qbase + (size_t)(q0 + row) * HID + c4 * 4);
        *reinterpret_cast<float4*>(&Ps[row * PSTR + c4 * 4]) = v;
    }
    __syncthreads();
    uint32_t qf[8][4];
    const int pr = wid * 16;
#pragma unroll
    for (int kt = 0; kt < 8; kt++) {
        qf[kt][0] = __float_as_uint(Ps[(pr + g)     * PSTR + kt * 8 + tig]);
        qf[kt][1] = __float_as_uint(Ps[(pr + 8 + g) * PSTR + kt * 8 + tig]);
        qf[kt][2] = __float_as_uint(Ps[(pr + g)     * PSTR + kt * 8 + tig + 4]);
        qf[kt][3] = __float_as_uint(Ps[(pr + 8 + g) * PSTR + kt * 8 + tig + 4]);
    }

    float m0r = -1e30f, m1r = -1e30f, l0 = 0.f, l1 = 0.f;
    float oacc[8][4];
#pragma unroll
    for (int i = 0; i < 8; i++)
#pragma unroll
        for (int j = 0; j < 4; j++) oacc[i][j] = 0.f;

    for (int nt = 0; nt < NT; nt++) {
        CP_WAIT(1);
        __syncthreads();                     // tile nt arrived (also covers Q staging)
        const float* Ks = smf + (nt & 1) * STGW;
        const float* Vs = Ks + VOFF;
        const float* Ms = Ks + MOFF;

        // ---- S = Q K^T
        float sf[8][4];
#pragma unroll
        for (int i = 0; i < 8; i++)
#pragma unroll
            for (int j = 0; j < 4; j++) sf[i][j] = 0.f;
#pragma unroll
        for (int kt = 0; kt < 8; kt++) {
#pragma unroll
            for (int sn = 0; sn < 8; sn++) {
                uint32_t kb[2];
                kb[0] = __float_as_uint(Ks[(sn * 8 + g) * KSTR + kt * 8 + tig]);
                kb[1] = __float_as_uint(Ks[(sn * 8 + g) * KSTR + kt * 8 + tig + 4]);
                mma_tf32(sf[sn], qf[kt], kb);
            }
        }

        // ---- online softmax (base-2 domain)
        float zmax0 = -1e30f, zmax1 = -1e30f;
#pragma unroll
        for (int sn = 0; sn < 8; sn++) {
            float mc0 = Ms[sn * 8 + 2 * tig]     * L2E;
            float mc1 = Ms[sn * 8 + 2 * tig + 1] * L2E;
            sf[sn][0] = sf[sn][0] * SCL + mc0;
            sf[sn][1] = sf[sn][1] * SCL + mc1;
            sf[sn][2] = sf[sn][2] * SCL + mc0;
            sf[sn][3] = sf[sn][3] * SCL + mc1;
            zmax0 = fmaxf(zmax0, fmaxf(sf[sn][0], sf[sn][1]));
            zmax1 = fmaxf(zmax1, fmaxf(sf[sn][2], sf[sn][3]));
        }
#pragma unroll
        for (int o2 = 1; o2 < 4; o2 <<= 1) {
            zmax0 = fmaxf(zmax0, __shfl_xor_sync(0xffffffffu, zmax0, o2));
            zmax1 = fmaxf(zmax1, __shfl_xor_sync(0xffffffffu, zmax1, o2));
        }
        float mn0 = fmaxf(m0r, zmax0), mn1 = fmaxf(m1r, zmax1);
        float al0 = exp2f(m0r - mn0), al1 = exp2f(m1r - mn1);
        m0r = mn0; m1r = mn1;

        float rs0 = 0.f, rs1 = 0.f;
#pragma unroll
        for (int sn = 0; sn < 8; sn++) {
            float p0 = exp2f(sf[sn][0] - mn0);
            float p1 = exp2f(sf[sn][1] - mn0);
            float p2 = exp2f(sf[sn][2] - mn1);
            float p3 = exp2f(sf[sn][3] - mn1);
            rs0 += p0 + p1; rs1 += p2 + p3;
            uint2 w0 = {f2tf(p0), f2tf(p1)};
            uint2 w1 = {f2tf(p2), f2tf(p3)};
            *reinterpret_cast<uint2*>(&Ps[(pr + g)     * PSTR + sn * 8 + 2 * tig]) = w0;
            *reinterpret_cast<uint2*>(&Ps[(pr + 8 + g) * PSTR + sn * 8 + 2 * tig]) = w1;
        }
#pragma unroll
        for (int o2 = 1; o2 < 4; o2 <<= 1) {
            rs0 += __shfl_xor_sync(0xffffffffu, rs0, o2);
            rs1 += __shfl_xor_sync(0xffffffffu, rs1, o2);
        }
        l0 = l0 * al0 + rs0;
        l1 = l1 * al1 + rs1;
#pragma unroll
        for (int dn = 0; dn < 8; dn++) {
            oacc[dn][0] *= al0; oacc[dn][1] *= al0;
            oacc[dn][2] *= al1; oacc[dn][3] *= al1;
        }
        __syncwarp();   // P stores visible within warp before A-frag reads

        // ---- O += P V
#pragma unroll
        for (int kt = 0; kt < 8; kt++) {
            uint32_t pa[4];
            pa[0] = __float_as_uint(Ps[(pr + g)     * PSTR + kt * 8 + tig]);
            pa[1] = __float_as_uint(Ps[(pr + 8 + g) * PSTR + kt * 8 + tig]);
            pa[2] = __float_as_uint(Ps[(pr + g)     * PSTR + kt * 8 + tig + 4]);
            pa[3] = __float_as_uint(Ps[(pr + 8 + g) * PSTR + kt * 8 + tig + 4]);
#pragma unroll
            for (int dn = 0; dn < 8; dn++) {
                uint32_t vb[2];
                vb[0] = __float_as_uint(Vs[(kt * 8 + tig)     * VSTR + dn * 8 + g]);
                vb[1] = __float_as_uint(Vs[(kt * 8 + tig + 4) * VSTR + dn * 8 + g]);
                mma_tf32(oacc[dn], pa, vb);
            }
        }
        __syncthreads();                     // all warps done with stage nt&1
        if (nt + 2 < NT) issue_tile(nt + 2); // refill into stage nt&1
        CP_COMMIT();
    }

    // ---- write context (exact + rounded copy for proj GEMM)
    float inv0 = 1.0f / l0, inv1 = 1.0f / l1;
    int r0 = b * SEQ + q0 + wid * 16 + g;
#pragma unroll
    for (int dn = 0; dn < 8; dn++) {
        int col = h * DH + dn * 8 + 2 * tig;
        float2 v0 = {oacc[dn][0] * inv0, oacc[dn][1] * inv0};
        float2 v1 = {oacc[dn][2] * inv1, oacc[dn][3] * inv1};
        float2 v0r = {f2tff(v0.x), f2tff(v0.y)};
        float2 v1r = {f2tff(v1.x), f2tff(v1.y)};
        *reinterpret_cast<float2*>(ctx  + (size_t)r0 * HID + col)       = v0;
        *reinterpret_cast<float2*>(ctx  + (size_t)(r0 + 8) * HID + col) = v1;
        *reinterpret_cast<float2*>(ctxr + (size_t)r0 * HID + col)       = v0r;
        *reinterpret_cast<float2*>(ctxr + (size_t)(r0 + 8) * HID + col) = v1r;
    }
}

// ===========================================================================
// Host side
// ===========================================================================
extern "C" void kernel_launch(void* const* d_in, const int* in_sizes, int n_in,
                              void* d_out, int out_size)
{
    const float* input = (const float*)d_in[0];
    const float* mask  = (const float*)d_in[1];
    const float* nw    = (const float*)d_in[2];
    const float* nb    = (const float*)d_in[3];
    const float* qkvw  = (const float*)d_in[4];
    const float* qkvb  = (const float*)d_in[5];
    const float* ow    = (const float*)d_in[6];

    float* out   = (float*)d_out;
    float* out_o = out;
    float* out_k = out + (size_t)TOK * HID;
    float* out_v = out + 2 * (size_t)TOK * HID;
    float* out_c = out + 3 * (size_t)TOK * HID;

    float *gq, *gln, *gkr, *gvr, *gcr, *gwq, *gwo;
    cudaGetSymbolAddress((void**)&gq,  g_q);
    cudaGetSymbolAddress((void**)&gln, g_ln);
    cudaGetSymbolAddress((void**)&gkr, g_kr);
    cudaGetSymbolAddress((void**)&gvr, g_vr);
    cudaGetSymbolAddress((void**)&gcr, g_cr);
    cudaGetSymbolAddress((void**)&gwq, g_wq);
    cudaGetSymbolAddress((void**)&gwo, g_wo);

    cudaFuncSetAttribute(gemm_mma<0>, cudaFuncAttributeMaxDynamicSharedMemorySize, GEMM_SMEM);
    cudaFuncSetAttribute(gemm_mma<1>, cudaFuncAttributeMaxDynamicSharedMemorySize, GEMM_SMEM);
    cudaFuncSetAttribute(attn_mma,    cudaFuncAttributeMaxDynamicSharedMemorySize, ATT_SMEM);

    round4_kernel<<<(3*HID*HID/4 + 255)/256, 256>>>(qkvw, gwq, 3*HID*HID/4);
    round4_kernel<<<(HID*HID/4 + 255)/256, 256>>>(ow, gwo, HID*HID/4);
    ln_kernel<<<TOK, 256>>>(input, nw, nb, gln);
    gemm_mma<0><<<dim3(TOK/128, 3*HID/128), 256, GEMM_SMEM>>>(
        gln, gwq, qkvb, gq, out_k, gkr, out_v, gvr, nullptr);
    attn_mma<<<dim3(SEQ/128, NHD, BSZ), 256, ATT_SMEM>>>(gq, gkr, gvr, mask, out_c, gcr);
    gemm_mma<1><<<dim3(TOK/128, HID/128), 256, GEMM_SMEM>>>(
        gcr, gwo, nullptr, nullptr, nullptr, nullptr, nullptr, nullptr, out_o);
}